// round 1
// baseline (speedup 1.0000x reference)
#include <cuda_runtime.h>
#include <cstdint>

#define BATCH 64
#define S_LEN 2048
#define HID   256

// ---------------------------------------------------------------------------
// f32x2 packed-math helpers (Blackwell fma.rn.f32x2: 2 independent fp32 FMAs)
// ---------------------------------------------------------------------------
__device__ __forceinline__ unsigned long long fma2(unsigned long long a,
                                                   unsigned long long b,
                                                   unsigned long long c) {
    unsigned long long d;
    asm("fma.rn.f32x2 %0, %1, %2, %3;" : "=l"(d) : "l"(a), "l"(b), "l"(c));
    return d;
}
__device__ __forceinline__ unsigned long long pack2(float x, float y) {
    unsigned long long r;
    asm("mov.b64 %0, {%1, %2};" : "=l"(r) : "f"(x), "f"(y));
    return r;
}
__device__ __forceinline__ float2 unpack2(unsigned long long v) {
    float2 r;
    asm("mov.b64 {%0, %1}, %2;" : "=f"(r.x), "=f"(r.y) : "l"(v));
    return r;
}

__device__ __forceinline__ unsigned smem_u32(const void* p) {
    return (unsigned)__cvta_generic_to_shared(p);
}
__device__ __forceinline__ unsigned mapa_peer(unsigned addr, unsigned rank) {
    unsigned r;
    asm("mapa.shared::cluster.u32 %0, %1, %2;" : "=r"(r) : "r"(addr), "r"(rank));
    return r;
}
__device__ __forceinline__ void st_cluster_f32(unsigned addr, float v) {
    asm volatile("st.shared::cluster.f32 [%0], %1;" :: "r"(addr), "f"(v) : "memory");
}
__device__ __forceinline__ void mbar_arrive_peer(unsigned addr) {
    asm volatile("mbarrier.arrive.release.cluster.shared::cluster.b64 _, [%0];"
                 :: "r"(addr) : "memory");
}
__device__ __forceinline__ void mbar_init(unsigned addr, unsigned count) {
    asm volatile("mbarrier.init.shared.b64 [%0], %1;" :: "r"(addr), "r"(count) : "memory");
}
__device__ __forceinline__ void mbar_wait_parity(unsigned addr, unsigned phase) {
    asm volatile(
        "{\n\t"
        ".reg .pred P;\n\t"
        "WL%=:\n\t"
        "mbarrier.try_wait.parity.acquire.cluster.shared::cta.b64 P, [%0], %1, 0x989680;\n\t"
        "@P bra WD%=;\n\t"
        "bra WL%=;\n\t"
        "WD%=:\n\t"
        "}" :: "r"(addr), "r"(phase) : "memory");
}
__device__ __forceinline__ void cluster_sync_all() {
    asm volatile("barrier.cluster.arrive.aligned;" ::: "memory");
    asm volatile("barrier.cluster.wait.aligned;" ::: "memory");
}

// ---------------------------------------------------------------------------
// Kernel 1: xW = X @ W_ih^T   (131072x256 @ 256x256) fp32, written into d_out
// Tile: 64m x 64h, k-chunks of 32, software-pipelined global loads,
// transposed smem staging, f32x2 inner product.
// ---------------------------------------------------------------------------
__global__ void __launch_bounds__(256) xw_gemm(const float* __restrict__ X,
                                               const float* __restrict__ Wih,
                                               float* __restrict__ out) {
    __shared__ alignas(16) float Xs[32][68];
    __shared__ alignas(16) float Ws[32][68];

    const int tid = threadIdx.x;
    const int m0  = blockIdx.x * 64;
    const int h0  = blockIdx.y * 64;
    const int row = tid >> 2;   // 0..63
    const int c4  = tid & 3;    // 0..3
    const int tx  = tid & 15;   // h micro-tile
    const int ty  = tid >> 4;   // m micro-tile

    unsigned long long acc[4][2];
#pragma unroll
    for (int i = 0; i < 4; i++) { acc[i][0] = 0ull; acc[i][1] = 0ull; }

    const float* Xbase = X   + (size_t)(m0 + row) * 256;
    const float* Wbase = Wih + (size_t)(h0 + row) * 256;

    // preload chunk 0
    float4 xa = *(const float4*)(Xbase + 0  + c4 * 4);
    float4 xb = *(const float4*)(Xbase + 16 + c4 * 4);
    float4 wa = *(const float4*)(Wbase + 0  + c4 * 4);
    float4 wb = *(const float4*)(Wbase + 16 + c4 * 4);

#pragma unroll 1
    for (int k0 = 0; k0 < 256; k0 += 32) {
        __syncthreads();  // previous chunk fully consumed
        // stage transposed: Xs[k][m], Ws[k][h]
#pragma unroll
        for (int e = 0; e < 4; e++) {
            Xs[c4 * 4 + e][row]      = (&xa.x)[e];
            Xs[16 + c4 * 4 + e][row] = (&xb.x)[e];
            Ws[c4 * 4 + e][row]      = (&wa.x)[e];
            Ws[16 + c4 * 4 + e][row] = (&wb.x)[e];
        }
        // prefetch next chunk (hidden under compute)
        float4 nxa = make_float4(0, 0, 0, 0), nxb = nxa, nwa = nxa, nwb = nxa;
        if (k0 < 224) {
            nxa = *(const float4*)(Xbase + k0 + 32 + c4 * 4);
            nxb = *(const float4*)(Xbase + k0 + 48 + c4 * 4);
            nwa = *(const float4*)(Wbase + k0 + 32 + c4 * 4);
            nwb = *(const float4*)(Wbase + k0 + 48 + c4 * 4);
        }
        __syncthreads();

#pragma unroll
        for (int kk = 0; kk < 32; kk++) {
            float4 a4 = *(const float4*)(&Xs[kk][ty * 4]);
            const unsigned long long* bp =
                (const unsigned long long*)(&Ws[kk][tx * 4]);
            unsigned long long b0 = bp[0];
            unsigned long long b1 = bp[1];
            unsigned long long aa;
            aa = pack2(a4.x, a4.x);
            acc[0][0] = fma2(aa, b0, acc[0][0]); acc[0][1] = fma2(aa, b1, acc[0][1]);
            aa = pack2(a4.y, a4.y);
            acc[1][0] = fma2(aa, b0, acc[1][0]); acc[1][1] = fma2(aa, b1, acc[1][1]);
            aa = pack2(a4.z, a4.z);
            acc[2][0] = fma2(aa, b0, acc[2][0]); acc[2][1] = fma2(aa, b1, acc[2][1]);
            aa = pack2(a4.w, a4.w);
            acc[3][0] = fma2(aa, b0, acc[3][0]); acc[3][1] = fma2(aa, b1, acc[3][1]);
        }
        xa = nxa; xb = nxb; wa = nwa; wb = nwb;
    }

#pragma unroll
    for (int i = 0; i < 4; i++) {
        float2 p = unpack2(acc[i][0]);
        float2 q = unpack2(acc[i][1]);
        float4 v = make_float4(p.x, p.y, q.x, q.y);
        *(float4*)(out + (size_t)(m0 + ty * 4 + i) * 256 + h0 + tx * 4) = v;
    }
}

// ---------------------------------------------------------------------------
// Kernel 2: the recurrence. One 2-CTA cluster per batch element.
// CTA rank r holds W_hh[:, r*128 : r*128+128) in REGISTERS (128 regs/thread),
// keeps h for its k-half in smem, exchanges cross-half partial sums per step
// via DSMEM stores + mbarrier. In-place: io holds xw on entry, tanh output on
// exit.
// ---------------------------------------------------------------------------
__global__ void __launch_bounds__(256, 1) __cluster_dims__(2, 1, 1)
rnn_scan(const float* __restrict__ Whh, float* __restrict__ io,
         float* __restrict__ hn) {
    __shared__ alignas(16) float h_own[128];
    __shared__ alignas(16) float recvbuf[2][128];
    __shared__ alignas(8) unsigned long long mbar[2];

    unsigned rank;
    asm("mov.u32 %0, %%cluster_ctarank;" : "=r"(rank));
    const int t = threadIdx.x;
    const int b = blockIdx.x >> 1;

    // load this thread's W row slice (output h = t, k in [rank*128, +128))
    unsigned long long w[64];
    {
        const float4* wrow =
            (const float4*)(Whh + (size_t)t * 256 + rank * 128);
#pragma unroll
        for (int i = 0; i < 32; i++) {
            float4 v = wrow[i];
            w[2 * i]     = pack2(v.x, v.y);
            w[2 * i + 1] = pack2(v.z, v.w);
        }
    }

    const bool mine = ((unsigned)t >> 7) == rank;  // this CTA finalizes h = t
    const int  slot = t & 127;

    if (t < 128) h_own[t] = 0.0f;  // h0 = 0
    if (t == 0) {
        mbar_init(smem_u32(&mbar[0]), 128);
        mbar_init(smem_u32(&mbar[1]), 128);
        asm volatile("fence.mbarrier_init.release.cluster;" ::: "memory");
    }
    __syncthreads();
    cluster_sync_all();  // mbarriers + h_own visible cluster-wide

    const unsigned peer = rank ^ 1u;
    const unsigned bar_local[2] = { smem_u32(&mbar[0]), smem_u32(&mbar[1]) };
    const unsigned bar_peer[2]  = { mapa_peer(bar_local[0], peer),
                                    mapa_peer(bar_local[1], peer) };
    const unsigned recv_peer[2] = {
        mapa_peer(smem_u32(&recvbuf[0][slot]), peer),
        mapa_peer(smem_u32(&recvbuf[1][slot]), peer)
    };

    float* xrow = io + (size_t)b * S_LEN * HID + t;  // column t, step stride HID
    float xw_cur = mine ? xrow[0] : 0.0f;

    const ulonglong2* h2 = (const ulonglong2*)h_own;

    for (int s = 0; s < S_LEN; s++) {
        // prefetch next step's xw early (hidden under the FMA loop)
        float xw_nxt = 0.0f;
        if (mine && s < S_LEN - 1) xw_nxt = xrow[(size_t)(s + 1) * HID];

        // partial_h(t) = sum over this CTA's k-half of h_prev[k] * W[t][k]
        unsigned long long a0 = 0ull, a1 = 0ull;
#pragma unroll
        for (int j = 0; j < 32; j++) {
            ulonglong2 hv = h2[j];  // 4 h values, broadcast LDS.128
            a0 = fma2(w[2 * j],     hv.x, a0);
            a1 = fma2(w[2 * j + 1], hv.y, a1);
        }
        float2 p0 = unpack2(a0);
        float2 p1 = unpack2(a1);
        float partial = (p0.x + p1.x) + (p0.y + p1.y);

        const int buf = s & 1;
        const unsigned ph = (unsigned)(s >> 1) & 1u;

        if (!mine) {
            // ship partial to the peer CTA that owns output h = t
            st_cluster_f32(recv_peer[buf], partial);
            mbar_arrive_peer(bar_peer[buf]);
        } else {
            mbar_wait_parity(bar_local[buf], ph);
            float v = tanhf(partial + recvbuf[buf][slot] + xw_cur);
            h_own[slot] = v;                       // h for next step (own half)
            xrow[(size_t)s * HID] = v;             // output[b][s][t] (in place)
            if (s == S_LEN - 1) hn[(size_t)b * HID + t] = v;
            xw_cur = xw_nxt;
        }
        __syncthreads();  // h_own(step s) complete before step s+1 reads
    }

    cluster_sync_all();  // no CTA exits while peer DSMEM traffic in flight
}

// ---------------------------------------------------------------------------
extern "C" void kernel_launch(void* const* d_in, const int* in_sizes, int n_in,
                              void* d_out, int out_size) {
    (void)in_sizes; (void)n_in; (void)out_size;
    const float* x   = (const float*)d_in[0];  // [64, 2048, 256]
    const float* wih = (const float*)d_in[1];  // [256, 256]
    const float* whh = (const float*)d_in[2];  // [256, 256]
    float* out = (float*)d_out;                           // output [64,2048,256]
    float* hn  = out + (size_t)BATCH * S_LEN * HID;       // h_n [1,64,256]

    dim3 grid_gemm(BATCH * S_LEN / 64, HID / 64);
    xw_gemm<<<grid_gemm, 256>>>(x, wih, out);

    rnn_scan<<<BATCH * 2, 256>>>(whh, out, hn);
}